// round 1
// baseline (speedup 1.0000x reference)
#include <cuda_runtime.h>
#include <math_constants.h>

#define N_IN    1024
#define N_OUT   4096
#define BF      64      // BATCH * FEAT = 2 * 32
#define M_TILE  32      // columns of B per block
#define CAP     64      // max nonzeros tracked per column (fallback if exceeded)
#define THREADS 256
#define BF_GROUP 8      // x rows staged in shared per phase-2 iteration

__global__ __launch_bounds__(THREADS)
void pool_clique_kernel(const float* __restrict__ x,
                        const float* __restrict__ B,
                        float* __restrict__ y)
{
    __shared__ unsigned short s_idx[M_TILE][CAP];   // 4 KB
    __shared__ int            s_cnt[M_TILE];
    __shared__ float          s_x[BF_GROUP][N_IN];  // 32 KB

    const int t    = threadIdx.x;
    const int lane = t & 31;
    const int warp = t >> 5;          // 0..7
    const int m0   = blockIdx.x * M_TILE;

    if (t < M_TILE) s_cnt[t] = 0;
    __syncthreads();

    // ---------------- Phase 1: compact nonzero row indices of B columns ----
    // Warp w scans rows n = w, w+8, w+16, ...; lane l owns column (m0 + l).
    // Each iteration the warp reads one contiguous 128B segment -> fully
    // coalesced; B is read exactly once chip-wide (16.8 MB).
    {
        const float* Bp = B + (size_t)m0 + lane;
        #pragma unroll 4
        for (int n = warp; n < N_IN; n += 8) {
            float v = Bp[(size_t)n * N_OUT];
            if (v != 0.0f) {
                int pos = atomicAdd(&s_cnt[lane], 1);
                if (pos < CAP) s_idx[lane][pos] = (unsigned short)n;
                // pos >= CAP: column falls back to dense scan in phase 2
            }
        }
    }
    __syncthreads();

    // ---------------- Phase 2: gather-max over staged x rows ---------------
    // 8 groups of 8 (b,f) rows. Thread (warp, lane) -> output (bf, column).
    for (int g = 0; g < BF; g += BF_GROUP) {
        // Stage 8 x rows (32 KB) into shared, vectorized.
        {
            const float4* xp = (const float4*)(x + (size_t)g * N_IN);
            float4*       sp = (float4*)&s_x[0][0];
            #pragma unroll
            for (int i = t; i < BF_GROUP * N_IN / 4; i += THREADS)
                sp[i] = xp[i];
        }
        __syncthreads();

        const int   m   = lane;
        const int   cnt = s_cnt[m];
        const float* xr = s_x[warp];
        float acc;

        if (cnt <= CAP) {
            // cnt < 1024 guarantees at least one zero product participates,
            // so the max starts at 0 (exact: x * 0 = +/-0, x * 1 = x).
            acc = 0.0f;
            const unsigned short* il = s_idx[m];
            for (int k = 0; k < cnt; k++)
                acc = fmaxf(acc, xr[il[k]]);
        } else {
            // Exact dense fallback (astronomically rare): recompute from B.
            acc = -CUDART_INF_F;
            const float* Bc = B + (size_t)m0 + m;
            for (int n = 0; n < N_IN; n++) {
                float bv = Bc[(size_t)n * N_OUT];
                acc = fmaxf(acc, bv * xr[n]);
            }
        }

        y[(size_t)(g + warp) * N_OUT + m0 + m] = acc;
        __syncthreads();   // protect s_x before next group's overwrite
    }
}

extern "C" void kernel_launch(void* const* d_in, const int* in_sizes, int n_in,
                              void* d_out, int out_size)
{
    const float* x = (const float*)d_in[0];   // (2, 32, 1024) f32
    const float* B = (const float*)d_in[1];   // (1024, 4096) f32
    float*       y = (float*)d_out;           // (2, 32, 4096) f32

    (void)in_sizes; (void)n_in; (void)out_size;
    pool_clique_kernel<<<N_OUT / M_TILE, THREADS>>>(x, B, y);
}

// round 2
// speedup vs baseline: 1.5699x; 1.5699x over previous
#include <cuda_runtime.h>
#include <math_constants.h>

#define N_IN    1024
#define N_OUT   4096
#define BF      64                  // BATCH * FEAT = 2 * 32
#define CAP     64                  // nonzeros tracked per column (dense fallback beyond)

// Scratch (device globals: allocation-free)
__device__ int            g_cnt[N_OUT];
__device__ unsigned short g_idx[N_OUT * CAP];
__device__ float          g_xt[N_IN * BF];     // x transposed: xt[n*BF + bf]

// ---------------------------------------------------------------------------
// Kernel 1: zero counters + transpose x (coalesced read, scattered 32B write;
// x is 256KB -> L2-resident, trivial).
// grid 256 x 256 = 65536 threads, one element each.
__global__ __launch_bounds__(256)
void prep_kernel(const float* __restrict__ x)
{
    int i = blockIdx.x * 256 + threadIdx.x;          // 0 .. 65535
    if (i < N_OUT) g_cnt[i] = 0;
    int bf = i >> 10;                                 // i / 1024
    int n  = i & 1023;
    g_xt[n * BF + bf] = x[i];                         // read coalesced
}

// ---------------------------------------------------------------------------
// Kernel 2: linear float4 scan of B, compact nonzero (n, m) pairs.
// 512 blocks x 256 threads, exactly 8 independent float4s per thread.
__global__ __launch_bounds__(256)
void scan_kernel(const float* __restrict__ B)
{
    const float4* B4 = (const float4*)B;
    int base = blockIdx.x * 256 + threadIdx.x;        // float4 index start
    #pragma unroll
    for (int it = 0; it < 8; it++) {
        int i4 = base + it * (512 * 256);             // 0 .. 2^20-1
        float4 v = B4[i4];
        if (v.x != 0.0f || v.y != 0.0f || v.z != 0.0f || v.w != 0.0f) {
            int n  = i4 >> 10;                        // row (4096/4 = 1024 float4/row)
            int m0 = (i4 & 1023) << 2;                // first of 4 columns
            float c[4] = {v.x, v.y, v.z, v.w};
            #pragma unroll
            for (int j = 0; j < 4; j++) {
                if (c[j] != 0.0f) {
                    int m   = m0 + j;
                    int pos = atomicAdd(&g_cnt[m], 1);
                    if (pos < CAP) g_idx[m * CAP + pos] = (unsigned short)n;
                }
            }
        }
    }
}

// ---------------------------------------------------------------------------
// Kernel 3: gather-max. Thread -> (m, bf), bf consecutive within a warp so
// each xt row access is a 128B contiguous warp load (L1/L2 hit).
// 1024 blocks x 256 threads: block covers 4 columns x 64 bf.
__global__ __launch_bounds__(256)
void gather_kernel(const float* __restrict__ B, float* __restrict__ y)
{
    int t  = threadIdx.x;
    int m  = blockIdx.x * 4 + (t >> 6);
    int bf = t & 63;

    int cnt = g_cnt[m];                               // broadcast across 64 threads
    float acc;

    if (cnt <= CAP) {
        // < N_IN nonzeros => at least one zero product participates => start at 0.
        acc = 0.0f;
        const unsigned short* il = &g_idx[m * CAP];
        const float*          xr = &g_xt[bf];
        int k = 0;
        for (; k + 4 <= cnt; k += 4) {                // 4 independent loads in flight
            float v0 = xr[(int)il[k + 0] * BF];
            float v1 = xr[(int)il[k + 1] * BF];
            float v2 = xr[(int)il[k + 2] * BF];
            float v3 = xr[(int)il[k + 3] * BF];
            acc = fmaxf(acc, fmaxf(fmaxf(v0, v1), fmaxf(v2, v3)));
        }
        for (; k < cnt; k++)
            acc = fmaxf(acc, xr[(int)il[k] * BF]);
    } else {
        // Exact dense fallback (astronomically rare).
        acc = -CUDART_INF_F;
        for (int n = 0; n < N_IN; n++)
            acc = fmaxf(acc, B[(size_t)n * N_OUT + m] * g_xt[n * BF + bf]);
    }

    y[(size_t)bf * N_OUT + m] = acc;
}

// ---------------------------------------------------------------------------
extern "C" void kernel_launch(void* const* d_in, const int* in_sizes, int n_in,
                              void* d_out, int out_size)
{
    const float* x = (const float*)d_in[0];   // (2, 32, 1024) f32
    const float* B = (const float*)d_in[1];   // (1024, 4096) f32
    float*       y = (float*)d_out;           // (2, 32, 4096) f32
    (void)in_sizes; (void)n_in; (void)out_size;

    prep_kernel  <<<256,  256>>>(x);
    scan_kernel  <<<512,  256>>>(B);
    gather_kernel<<<1024, 256>>>(B, y);
}

// round 3
// speedup vs baseline: 1.6141x; 1.0281x over previous
#include <cuda_runtime.h>
#include <math_constants.h>

#define N_IN    1024
#define N_OUT   4096
#define BF      64                  // BATCH * FEAT
#define CAP     64                  // nonzeros tracked per column (dense fallback beyond)
#define M_TILE  32                  // columns per gather block

// Scratch (device globals, zero-initialized at module load; gather re-zeroes
// g_cnt after use so every launch sees zeroed counters -> deterministic).
__device__ int            g_cnt[N_OUT];
__device__ unsigned short g_idx[N_OUT * CAP];
__device__ float          g_xt[N_IN * BF];     // x transposed: xt[n*BF + bf]

// ---------------------------------------------------------------------------
// Kernel 1: linear float4 scan of B (8 independent LDG.128 per thread, issued
// up-front for max MLP) + compact nonzero (n,m) pairs via global atomics.
// First 256 blocks also transpose x into g_xt (64K elements, 1/thread).
__global__ __launch_bounds__(256)
void scan_kernel(const float* __restrict__ B, const float* __restrict__ x)
{
    const int t = threadIdx.x;
    const int b = blockIdx.x;

    // Fold in the x transpose (no separate prep launch).
    if (b < 256) {
        int i  = b * 256 + t;                 // 0 .. 65535
        int bf = i >> 10;
        int n  = i & 1023;
        g_xt[n * BF + bf] = x[i];
    }

    // Preload 8 float4s (stride 512*256 float4s apart) before any branching.
    const float4* B4 = (const float4*)B;
    int base = b * 256 + t;
    float4 v[8];
    #pragma unroll
    for (int it = 0; it < 8; it++)
        v[it] = B4[base + it * (512 * 256)];

    #pragma unroll
    for (int it = 0; it < 8; it++) {
        if (v[it].x != 0.0f || v[it].y != 0.0f || v[it].z != 0.0f || v[it].w != 0.0f) {
            int i4 = base + it * (512 * 256);
            int n  = i4 >> 10;                 // 1024 float4 per row
            int m0 = (i4 & 1023) << 2;
            float c[4] = {v[it].x, v[it].y, v[it].z, v[it].w};
            #pragma unroll
            for (int j = 0; j < 4; j++) {
                if (c[j] != 0.0f) {
                    int pos = atomicAdd(&g_cnt[m0 + j], 1);
                    if (pos < CAP) g_idx[(m0 + j) * CAP + pos] = (unsigned short)n;
                }
            }
        }
    }
}

// ---------------------------------------------------------------------------
// Kernel 2: gather-max. 128 blocks x 256 threads; block = 32 columns x 64 bf.
// Thread (m_local = t>>3, bf octet = (t&7)*8): each index gathers
// xt[n][bf0..bf0+7] as two aligned float4 loads. Results staged in shared,
// written out as coalesced 128B row segments. Also resets g_cnt to 0.
__global__ __launch_bounds__(256)
void gather_kernel(const float* __restrict__ B, float* __restrict__ y)
{
    __shared__ int            s_cnt[M_TILE];
    __shared__ unsigned short s_idx[M_TILE][CAP];   // 4 KB
    __shared__ float          s_out[BF][M_TILE];    // 8 KB

    const int t  = threadIdx.x;
    const int m0 = blockIdx.x * M_TILE;

    // Load counters; reset for the next launch (module-load state is zero).
    if (t < M_TILE) {
        s_cnt[t] = g_cnt[m0 + t];
        g_cnt[m0 + t] = 0;
    }
    // Load index lists (32 cols x 64 ushort = 4KB) as coalesced uints.
    {
        const unsigned int* src = (const unsigned int*)&g_idx[m0 * CAP];
        unsigned int*       dst = (unsigned int*)&s_idx[0][0];
        #pragma unroll
        for (int i = 0; i < 4; i++)
            dst[t + i * 256] = src[t + i * 256];
    }
    __syncthreads();

    const int   ml  = t >> 3;          // 0..31 column within tile
    const int   bf0 = (t & 7) * 8;     // bf octet base
    const int   cnt = s_cnt[ml];

    float acc[8];
    #pragma unroll
    for (int j = 0; j < 8; j++) acc[j] = 0.0f;

    if (cnt <= CAP) {
        // cnt < N_IN => at least one zero product participates => start at 0.
        const float4* xt4 = (const float4*)g_xt;
        for (int k = 0; k < cnt; k++) {
            int n = s_idx[ml][k];
            float4 a = xt4[(n * BF + bf0) >> 2];
            float4 c = xt4[((n * BF + bf0) >> 2) + 1];
            acc[0] = fmaxf(acc[0], a.x);  acc[1] = fmaxf(acc[1], a.y);
            acc[2] = fmaxf(acc[2], a.z);  acc[3] = fmaxf(acc[3], a.w);
            acc[4] = fmaxf(acc[4], c.x);  acc[5] = fmaxf(acc[5], c.y);
            acc[6] = fmaxf(acc[6], c.z);  acc[7] = fmaxf(acc[7], c.w);
        }
    } else {
        // Exact dense fallback (astronomically rare).
        #pragma unroll
        for (int j = 0; j < 8; j++) acc[j] = -CUDART_INF_F;
        for (int n = 0; n < N_IN; n++) {
            float bv = B[(size_t)n * N_OUT + m0 + ml];
            #pragma unroll
            for (int j = 0; j < 8; j++)
                acc[j] = fmaxf(acc[j], bv * g_xt[n * BF + bf0 + j]);
        }
    }

    #pragma unroll
    for (int j = 0; j < 8; j++)
        s_out[bf0 + j][ml] = acc[j];
    __syncthreads();

    // Coalesced write: warp w writes rows {w, w+8, ...}, lane -> column.
    const int lane = t & 31;
    const int warp = t >> 5;
    #pragma unroll
    for (int r = 0; r < 8; r++) {
        int row = warp + r * 8;                    // bf
        y[(size_t)row * N_OUT + m0 + lane] = s_out[row][lane];
    }
}

// ---------------------------------------------------------------------------
extern "C" void kernel_launch(void* const* d_in, const int* in_sizes, int n_in,
                              void* d_out, int out_size)
{
    const float* x = (const float*)d_in[0];   // (2, 32, 1024) f32
    const float* B = (const float*)d_in[1];   // (1024, 4096) f32
    float*       y = (float*)d_out;           // (2, 32, 4096) f32
    (void)in_sizes; (void)n_in; (void)out_size;

    scan_kernel  <<<512, 256>>>(B, x);
    gather_kernel<<<128, 256>>>(B, y);
}

// round 4
// speedup vs baseline: 2.0176x; 1.2500x over previous
#include <cuda_runtime.h>
#include <math_constants.h>

#define N_IN    1024
#define N_OUT   4096
#define BF      64                  // BATCH * FEAT
#define CAP     64                  // nonzeros tracked per column (dense fallback beyond)
#define GM_TILE 8                   // columns per gather block

// Scratch (device globals, zero-initialized at module load; gather re-zeroes
// g_cnt after use so every launch sees zeroed counters -> deterministic).
__device__ int            g_cnt[N_OUT];
__device__ unsigned short g_idx[N_OUT * CAP];
__device__ float          g_xt[N_IN * BF];     // x transposed: xt[n*BF + bf]

// ---------------------------------------------------------------------------
// Kernel 1: linear float4 scan of B. 1024 blocks x 256 threads, 4 independent
// LDG.128 per thread preloaded up-front. Nonzero (n,m) pairs compacted via
// global atomics (~10 per column). First 256 blocks also transpose x.
__global__ __launch_bounds__(256)
void scan_kernel(const float* __restrict__ B, const float* __restrict__ x)
{
    const int t = threadIdx.x;
    const int b = blockIdx.x;

    // Fold in the x transpose (no separate prep launch).
    if (b < 256) {
        int i  = b * 256 + t;                 // 0 .. 65535
        int bf = i >> 10;
        int n  = i & 1023;
        g_xt[n * BF + bf] = x[i];
    }

    const float4* B4 = (const float4*)B;
    const int base = b * 256 + t;
    float4 v[4];
    #pragma unroll
    for (int it = 0; it < 4; it++)
        v[it] = B4[base + it * (1024 * 256)];  // covers 2^20 float4 = 16.8MB

    #pragma unroll
    for (int it = 0; it < 4; it++) {
        if (v[it].x != 0.0f || v[it].y != 0.0f || v[it].z != 0.0f || v[it].w != 0.0f) {
            int i4 = base + it * (1024 * 256);
            int n  = i4 >> 10;                 // 1024 float4 per row
            int m0 = (i4 & 1023) << 2;
            float c[4] = {v[it].x, v[it].y, v[it].z, v[it].w};
            #pragma unroll
            for (int j = 0; j < 4; j++) {
                if (c[j] != 0.0f) {
                    int pos = atomicAdd(&g_cnt[m0 + j], 1);
                    if (pos < CAP) g_idx[(m0 + j) * CAP + pos] = (unsigned short)n;
                }
            }
        }
    }
}

// ---------------------------------------------------------------------------
// Kernel 2: gather-max. 512 blocks x 256 threads; block = 8 columns x 64 bf.
// Thread (col = t>>5, lane -> bf pair 2l,2l+1): cnt independent float2 loads
// from g_xt (whole warp touches 2 lines per index). Coalesced staged output.
__global__ __launch_bounds__(256)
void gather_kernel(const float* __restrict__ B, float* __restrict__ y)
{
    __shared__ int            s_cnt[GM_TILE];
    __shared__ unsigned short s_idx[GM_TILE][CAP];   // 1 KB
    __shared__ float          s_out[BF][GM_TILE];    // 2 KB

    const int t  = threadIdx.x;
    const int m0 = blockIdx.x * GM_TILE;

    if (t < GM_TILE) {
        s_cnt[t] = g_cnt[m0 + t];
        g_cnt[m0 + t] = 0;                     // reset for next launch
    }
    // Stage index lists: 8 cols x 64 ushort = 256 uints, one per thread.
    ((unsigned int*)&s_idx[0][0])[t] = ((const unsigned int*)&g_idx[m0 * CAP])[t];
    __syncthreads();

    const int col  = t >> 5;                   // 0..7
    const int lane = t & 31;                   // bf pair = 2*lane, 2*lane+1
    const int cnt  = s_cnt[col];

    float2 acc = make_float2(0.0f, 0.0f);

    if (cnt <= CAP) {
        // cnt < N_IN => at least one zero product participates => start at 0.
        const float2* xt2 = (const float2*)g_xt;   // row n at offset n*32
        const unsigned short* il = s_idx[col];
        int k = 0;
        #pragma unroll 1
        for (; k + 4 <= cnt; k += 4) {             // 4 independent loads in flight
            float2 v0 = xt2[(int)il[k + 0] * 32 + lane];
            float2 v1 = xt2[(int)il[k + 1] * 32 + lane];
            float2 v2 = xt2[(int)il[k + 2] * 32 + lane];
            float2 v3 = xt2[(int)il[k + 3] * 32 + lane];
            acc.x = fmaxf(acc.x, fmaxf(fmaxf(v0.x, v1.x), fmaxf(v2.x, v3.x)));
            acc.y = fmaxf(acc.y, fmaxf(fmaxf(v0.y, v1.y), fmaxf(v2.y, v3.y)));
        }
        for (; k < cnt; k++) {
            float2 v = xt2[(int)il[k] * 32 + lane];
            acc.x = fmaxf(acc.x, v.x);
            acc.y = fmaxf(acc.y, v.y);
        }
    } else {
        // Exact dense fallback (astronomically rare).
        acc = make_float2(-CUDART_INF_F, -CUDART_INF_F);
        const float2* xt2 = (const float2*)g_xt;
        for (int n = 0; n < N_IN; n++) {
            float  bv = B[(size_t)n * N_OUT + m0 + col];
            float2 v  = xt2[n * 32 + lane];
            acc.x = fmaxf(acc.x, bv * v.x);
            acc.y = fmaxf(acc.y, bv * v.y);
        }
    }

    s_out[2 * lane    ][col] = acc.x;
    s_out[2 * lane + 1][col] = acc.y;
    __syncthreads();

    // Write 64 rows x 8 cols: thread -> (bf = t>>2, pair j = (t&3)*2).
    // Aligned float2 stores; each row is a full 32B sector.
    {
        const int bf = t >> 2;
        const int j  = (t & 3) * 2;
        float2 w = make_float2(s_out[bf][j], s_out[bf][j + 1]);
        *(float2*)&y[(size_t)bf * N_OUT + m0 + j] = w;
    }
}

// ---------------------------------------------------------------------------
extern "C" void kernel_launch(void* const* d_in, const int* in_sizes, int n_in,
                              void* d_out, int out_size)
{
    const float* x = (const float*)d_in[0];   // (2, 32, 1024) f32
    const float* B = (const float*)d_in[1];   // (1024, 4096) f32
    float*       y = (float*)d_out;           // (2, 32, 4096) f32
    (void)in_sizes; (void)n_in; (void)out_size;

    scan_kernel  <<<1024, 256>>>(B, x);
    gather_kernel<<<512,  256>>>(B, y);
}